// round 11
// baseline (speedup 1.0000x reference)
#include <cuda_runtime.h>
#include <math.h>

#define V_SZ 50257
#define E_SZ 512
#define H_SZ 512
#define N_B 32
#define T_SZ 128
#define NSTEP 127
#define NROWS 4064
#define NROWS_PAD 4096
#define C3H 1536
#define NBLK_V 393
#define REC_CTAS 128

__device__ float g_gi[NROWS_PAD * C3H];
__device__ float g_hall[(NROWS_PAD + N_B) * H_SZ];   // step s at offset s*N_B*H_SZ; pad rows stay 0
__device__ float g_pmax[NBLK_V * NROWS_PAD];
__device__ float g_psum[NBLK_V * NROWS_PAD];
__device__ float g_tlog[NROWS];
__device__ float g_ll[NROWS];
__device__ unsigned int g_barcnt;
__device__ unsigned int g_bargen;

// ---------------- kernel 1: gi = gather(embW,words) @ Wih^T + bih ----------------
__global__ __launch_bounds__(256) void k_gi(const int* __restrict__ words,
                                            const float* __restrict__ embW,
                                            const float* __restrict__ Wih,
                                            const float* __restrict__ bih) {
    __shared__ float As[16 * 128];
    __shared__ float Bs[16 * 128];
    int tid = threadIdx.x, tx = tid & 15, ty = tid >> 4;
    int mblk = blockIdx.x, nblk = blockIdx.y;
    float acc[8][8];
#pragma unroll
    for (int i = 0; i < 8; i++)
#pragma unroll
        for (int j = 0; j < 8; j++) acc[i][j] = 0.f;

    for (int kb = 0; kb < E_SZ; kb += 16) {
#pragma unroll
        for (int u = 0; u < 2; u++) {
            int idx = tid + u * 256, row = idx >> 2, kq = idx & 3;
            int r = mblk * 128 + row;
            int w = (r < NROWS) ? words[(r & 31) * T_SZ + (r >> 5)] : 0;
            float4 v = *(const float4*)(embW + (size_t)w * E_SZ + kb + kq * 4);
            if (r >= NROWS) v = make_float4(0.f, 0.f, 0.f, 0.f);
            As[(kq * 4 + 0) * 128 + row] = v.x;
            As[(kq * 4 + 1) * 128 + row] = v.y;
            As[(kq * 4 + 2) * 128 + row] = v.z;
            As[(kq * 4 + 3) * 128 + row] = v.w;
        }
#pragma unroll
        for (int u = 0; u < 2; u++) {
            int idx = tid + u * 256, col = idx >> 2, kq = idx & 3;
            int c = nblk * 128 + col;
            float4 v = *(const float4*)(Wih + (size_t)c * E_SZ + kb + kq * 4);
            Bs[(kq * 4 + 0) * 128 + col] = v.x;
            Bs[(kq * 4 + 1) * 128 + col] = v.y;
            Bs[(kq * 4 + 2) * 128 + col] = v.z;
            Bs[(kq * 4 + 3) * 128 + col] = v.w;
        }
        __syncthreads();
#pragma unroll
        for (int k = 0; k < 16; k++) {
            float a[8], bb[8];
            *(float4*)(a)      = *(const float4*)&As[k * 128 + ty * 4];
            *(float4*)(a + 4)  = *(const float4*)&As[k * 128 + 64 + ty * 4];
            *(float4*)(bb)     = *(const float4*)&Bs[k * 128 + tx * 4];
            *(float4*)(bb + 4) = *(const float4*)&Bs[k * 128 + 64 + tx * 4];
#pragma unroll
            for (int i = 0; i < 8; i++)
#pragma unroll
                for (int j = 0; j < 8; j++) acc[i][j] += a[i] * bb[j];
        }
        __syncthreads();
    }
#pragma unroll
    for (int i = 0; i < 8; i++) {
        int r = mblk * 128 + ((i < 4) ? ty * 4 + i : 64 + ty * 4 + (i - 4));
#pragma unroll
        for (int j = 0; j < 8; j++) {
            int c = nblk * 128 + ((j < 4) ? tx * 4 + j : 64 + tx * 4 + (j - 4));
            g_gi[(size_t)r * C3H + c] = acc[i][j] + bih[c];
        }
    }
}

// ---------------- grid barrier ----------------
__device__ __forceinline__ void gridbar() {
    __syncthreads();
    if (threadIdx.x == 0) {
        unsigned int gen = *((volatile unsigned int*)&g_bargen);
        __threadfence();
        unsigned int t = atomicAdd(&g_barcnt, 1u);
        if (t == REC_CTAS - 1) {
            g_barcnt = 0;
            __threadfence();
            *((volatile unsigned int*)&g_bargen) = gen + 1;
        } else {
            while (*((volatile unsigned int*)&g_bargen) == gen) { __nanosleep(64); }
        }
        __threadfence();
    }
    __syncthreads();
}

// ---------------- kernel 2: persistent GRU recurrence ----------------
__global__ __launch_bounds__(256) void k_rec(const float* __restrict__ h0,
                                             const float* __restrict__ Whh,
                                             const float* __restrict__ bhh) {
    extern __shared__ float sm[];
    float* sW   = sm;                  // 512*12
    float* sH   = sW + 512 * 12;       // 32*513
    float* red  = sH + 32 * 513;       // 256*12
    float* ghs  = red + 256 * 12;      // 384
    float* sbhh = ghs + 384;           // 12

    int tid = threadIdx.x, cta = blockIdx.x;

    for (int i = tid; i < 12 * 512; i += 256) {
        int cl = i >> 9, k = i & 511;
        int row = (cl >> 2) * H_SZ + cta * 4 + (cl & 3);
        sW[k * 12 + cl] = Whh[(size_t)row * H_SZ + k];
    }
    if (tid < 12) sbhh[tid] = bhh[(tid >> 2) * H_SZ + cta * 4 + (tid & 3)];

    for (int i = tid; i < 128; i += 256) g_hall[cta * 128 + i] = h0[cta * 128 + i];
    __threadfence();
    gridbar();

    int lane = tid & 31, wid = tid >> 5;
    int bq = lane & 7, cg = lane >> 3, k0 = wid * 64;

    for (int t = 0; t < NSTEP; t++) {
        const float* hsrc = g_hall + (size_t)t * N_B * H_SZ;
        for (int i = tid; i < N_B * H_SZ / 4; i += 256) {
            float4 v = ((const float4*)hsrc)[i];
            int flat = i * 4, b = flat >> 9, k = flat & 511;
            float* p = &sH[b * 513 + k];
            p[0] = v.x; p[1] = v.y; p[2] = v.z; p[3] = v.w;
        }
        __syncthreads();

        float acc[3][4];
#pragma unroll
        for (int c = 0; c < 3; c++)
#pragma unroll
            for (int b = 0; b < 4; b++) acc[c][b] = 0.f;

#pragma unroll 4
        for (int kk = 0; kk < 64; kk++) {
            int k = k0 + kk;
            float h0v = sH[(bq * 4 + 0) * 513 + k];
            float h1v = sH[(bq * 4 + 1) * 513 + k];
            float h2v = sH[(bq * 4 + 2) * 513 + k];
            float h3v = sH[(bq * 4 + 3) * 513 + k];
            float w0 = sW[k * 12 + cg * 3 + 0];
            float w1 = sW[k * 12 + cg * 3 + 1];
            float w2 = sW[k * 12 + cg * 3 + 2];
            acc[0][0] += h0v * w0; acc[0][1] += h1v * w0; acc[0][2] += h2v * w0; acc[0][3] += h3v * w0;
            acc[1][0] += h0v * w1; acc[1][1] += h1v * w1; acc[1][2] += h2v * w1; acc[1][3] += h3v * w1;
            acc[2][0] += h0v * w2; acc[2][1] += h1v * w2; acc[2][2] += h2v * w2; acc[2][3] += h3v * w2;
        }
        {
            float* rp = &red[tid * 12];
#pragma unroll
            for (int c = 0; c < 3; c++)
#pragma unroll
                for (int b = 0; b < 4; b++) rp[c * 4 + b] = acc[c][b];
        }
        __syncthreads();

        for (int o = tid; o < 384; o += 256) {
            int cl = o >> 5, b = o & 31;
            int l = (b >> 2) + 8 * (cl / 3);
            int a = (cl % 3) * 4 + (b & 3);
            float s = 0.f;
#pragma unroll
            for (int w = 0; w < 8; w++) s += red[(w * 32 + l) * 12 + a];
            ghs[o] = s;
        }
        __syncthreads();

        if (tid < 128) {
            int jl = tid >> 5, b = tid & 31;
            float ghr = ghs[(0 + jl) * 32 + b] + sbhh[0 + jl];
            float ghz = ghs[(4 + jl) * 32 + b] + sbhh[4 + jl];
            float ghn = ghs[(8 + jl) * 32 + b] + sbhh[8 + jl];
            const float* gi = &g_gi[(size_t)(t * N_B + b) * C3H + cta * 4 + jl];
            float r = 1.f / (1.f + expf(-(gi[0] + ghr)));
            float z = 1.f / (1.f + expf(-(gi[512] + ghz)));
            float n = tanhf(gi[1024] + r * ghn);
            float hold = sH[b * 513 + (cta * 4 + jl)];
            g_hall[(size_t)(t + 1) * N_B * H_SZ + (size_t)b * H_SZ + cta * 4 + jl] =
                (1.f - z) * n + z * hold;
        }
        __threadfence();
        gridbar();
    }
}

// ---------------- kernel 3: target logits ----------------
__global__ __launch_bounds__(256) void k_tgt(const int* __restrict__ words,
                                             const float* __restrict__ emW,
                                             const float* __restrict__ emb) {
    int gw = blockIdx.x * 8 + (threadIdx.x >> 5);
    int lane = threadIdx.x & 31;
    if (gw >= NROWS) return;
    int t = gw >> 5, b = gw & 31;
    int tgt = words[b * T_SZ + t + 1];
    const float* hr = g_hall + (size_t)(gw + N_B) * H_SZ;
    const float* wr = emW + (size_t)tgt * E_SZ;
    float s = 0.f;
#pragma unroll
    for (int q = 0; q < 4; q++) {
        int k = q * 128 + lane * 4;
        float4 hv = *(const float4*)(hr + k);
        float4 wv = *(const float4*)(wr + k);
        s += hv.x * wv.x + hv.y * wv.y + hv.z * wv.z + hv.w * wv.w;
    }
#pragma unroll
    for (int off = 16; off; off >>= 1) s += __shfl_down_sync(0xffffffffu, s, off);
    if (lane == 0) g_tlog[gw] = s + emb[tgt];
}

// ---------------- kernel 4: logits GEMM + fused partial logsumexp ----------------
__global__ __launch_bounds__(256) void k_logits(const float* __restrict__ emW,
                                                const float* __restrict__ emb) {
    __shared__ float As[16 * 128];
    __shared__ float Bs[16 * 128];
    __shared__ float red[128 * 16];
    __shared__ float rowst[128];
    const float* Amat = g_hall + N_B * H_SZ;

    int tid = threadIdx.x, tx = tid & 15, ty = tid >> 4;
    int mblk = blockIdx.x, nblk = blockIdx.y;
    float acc[8][8];
#pragma unroll
    for (int i = 0; i < 8; i++)
#pragma unroll
        for (int j = 0; j < 8; j++) acc[i][j] = 0.f;

    for (int kb = 0; kb < E_SZ; kb += 16) {
#pragma unroll
        for (int u = 0; u < 2; u++) {
            int idx = tid + u * 256, row = idx >> 2, kq = idx & 3;
            float4 v = *(const float4*)(Amat + (size_t)(mblk * 128 + row) * E_SZ + kb + kq * 4);
            As[(kq * 4 + 0) * 128 + row] = v.x;
            As[(kq * 4 + 1) * 128 + row] = v.y;
            As[(kq * 4 + 2) * 128 + row] = v.z;
            As[(kq * 4 + 3) * 128 + row] = v.w;
        }
#pragma unroll
        for (int u = 0; u < 2; u++) {
            int idx = tid + u * 256, col = idx >> 2, kq = idx & 3;
            int c = nblk * 128 + col;
            float4 v = make_float4(0.f, 0.f, 0.f, 0.f);
            if (c < V_SZ) v = *(const float4*)(emW + (size_t)c * E_SZ + kb + kq * 4);
            Bs[(kq * 4 + 0) * 128 + col] = v.x;
            Bs[(kq * 4 + 1) * 128 + col] = v.y;
            Bs[(kq * 4 + 2) * 128 + col] = v.z;
            Bs[(kq * 4 + 3) * 128 + col] = v.w;
        }
        __syncthreads();
#pragma unroll
        for (int k = 0; k < 16; k++) {
            float a[8], bb[8];
            *(float4*)(a)      = *(const float4*)&As[k * 128 + ty * 4];
            *(float4*)(a + 4)  = *(const float4*)&As[k * 128 + 64 + ty * 4];
            *(float4*)(bb)     = *(const float4*)&Bs[k * 128 + tx * 4];
            *(float4*)(bb + 4) = *(const float4*)&Bs[k * 128 + 64 + tx * 4];
#pragma unroll
            for (int i = 0; i < 8; i++)
#pragma unroll
                for (int j = 0; j < 8; j++) acc[i][j] += a[i] * bb[j];
        }
        __syncthreads();
    }

    int colg[8], rowl[8]; float bj[8];
#pragma unroll
    for (int j = 0; j < 8; j++) {
        int c = nblk * 128 + ((j < 4) ? tx * 4 + j : 64 + tx * 4 + (j - 4));
        colg[j] = c;
        bj[j] = (c < V_SZ) ? emb[c] : 0.f;
    }
#pragma unroll
    for (int i = 0; i < 8; i++) rowl[i] = (i < 4) ? ty * 4 + i : 64 + ty * 4 + (i - 4);
#pragma unroll
    for (int i = 0; i < 8; i++)
#pragma unroll
        for (int j = 0; j < 8; j++) acc[i][j] += bj[j];

#pragma unroll
    for (int i = 0; i < 8; i++) {
        float m = -3.0e38f;
#pragma unroll
        for (int j = 0; j < 8; j++)
            if (colg[j] < V_SZ) m = fmaxf(m, acc[i][j]);
        red[rowl[i] * 16 + tx] = m;
    }
    __syncthreads();
    if (tid < 128) {
        float m = -3.0e38f;
#pragma unroll
        for (int x = 0; x < 16; x++) m = fmaxf(m, red[tid * 16 + x]);
        rowst[tid] = m;
    }
    __syncthreads();
#pragma unroll
    for (int i = 0; i < 8; i++) {
        float m = rowst[rowl[i]];
        float s = 0.f;
#pragma unroll
        for (int j = 0; j < 8; j++)
            if (colg[j] < V_SZ) s += expf(acc[i][j] - m);
        red[rowl[i] * 16 + tx] = s;
    }
    __syncthreads();
    if (tid < 128) {
        float s = 0.f;
#pragma unroll
        for (int x = 0; x < 16; x++) s += red[tid * 16 + x];
        int rg = mblk * 128 + tid;
        g_pmax[(size_t)nblk * NROWS_PAD + rg] = rowst[tid];
        g_psum[(size_t)nblk * NROWS_PAD + rg] = s;
    }
}

// ---------------- kernel 5: combine partials -> ll ----------------
__global__ __launch_bounds__(256) void k_fin1() {
    int row = blockIdx.x * 256 + threadIdx.x;
    if (row >= NROWS) return;
    float m = -3.0e38f;
    for (int blk = 0; blk < NBLK_V; blk++)
        m = fmaxf(m, g_pmax[(size_t)blk * NROWS_PAD + row]);
    float s = 0.f;
    for (int blk = 0; blk < NBLK_V; blk++)
        s += g_psum[(size_t)blk * NROWS_PAD + row] *
             expf(g_pmax[(size_t)blk * NROWS_PAD + row] - m);
    g_ll[row] = g_tlog[row] - (m + logf(s));
}

// ---------------- kernel 6: outputs ----------------
__global__ __launch_bounds__(256) void k_out(float* __restrict__ out) {
    int i = blockIdx.x * 256 + threadIdx.x;
    if (i < 32) {
        float s = 0.f;
        for (int t = 0; t < NSTEP; t++) s += g_ll[t * 32 + i];
        out[i] = s * (1.0f / (float)NSTEP);
    }
    int j = i - 32;
    if (j >= 0 && j < N_B * H_SZ)
        out[32 + j] = g_hall[(size_t)NSTEP * N_B * H_SZ + j];
}

extern "C" void kernel_launch(void* const* d_in, const int* in_sizes, int n_in,
                              void* d_out, int out_size) {
    const int*   words = (const int*)d_in[0];
    const float* h0    = (const float*)d_in[1];
    const float* embW  = (const float*)d_in[2];
    const float* Wih   = (const float*)d_in[3];
    const float* Whh   = (const float*)d_in[4];
    const float* bih   = (const float*)d_in[5];
    const float* bhh   = (const float*)d_in[6];
    const float* emW   = (const float*)d_in[7];
    const float* emb   = (const float*)d_in[8];
    float* out = (float*)d_out;

    const int rec_smem = (512 * 12 + 32 * 513 + 256 * 12 + 384 + 12) * 4;
    cudaFuncSetAttribute(k_rec, cudaFuncAttributeMaxDynamicSharedMemorySize, rec_smem);

    k_gi<<<dim3(32, 12), 256>>>(words, embW, Wih, bih);
    k_rec<<<REC_CTAS, 256, rec_smem>>>(h0, Whh, bhh);
    k_tgt<<<(NROWS + 7) / 8, 256>>>(words, emW, emb);
    k_logits<<<dim3(32, NBLK_V), 256>>>(emW, emb);
    k_fin1<<<(NROWS + 255) / 256, 256>>>();
    k_out<<<(32 + N_B * H_SZ + 255) / 256, 256>>>(out);
}

// round 17
// speedup vs baseline: 1.8493x; 1.8493x over previous
#include <cuda_runtime.h>
#include <math.h>
#include <stdint.h>

#define V_SZ 50257
#define E_SZ 512
#define H_SZ 512
#define N_B 32
#define T_SZ 128
#define NSTEP 127
#define NROWS 4064
#define NROWS_PAD 4096
#define C3H 1536
#define NBLK_V 393
#define REC_CTAS 128

__device__ float g_gi[NROWS_PAD * C3H];
__device__ float g_hall[(NROWS_PAD + N_B) * H_SZ];   // step s at offset s*N_B*H_SZ; pad rows stay 0
__device__ float g_pmax[NBLK_V * NROWS_PAD];
__device__ float g_psum[NBLK_V * NROWS_PAD];
__device__ float g_tlog[NROWS];
__device__ float g_ll[NROWS];
__device__ unsigned int g_barcnt;
__device__ unsigned int g_bargen;

// ---------------- kernel 1: gi = gather(embW,words) @ Wih^T + bih ----------------
__global__ __launch_bounds__(256) void k_gi(const int* __restrict__ words,
                                            const float* __restrict__ embW,
                                            const float* __restrict__ Wih,
                                            const float* __restrict__ bih) {
    __shared__ float As[16 * 128];
    __shared__ float Bs[16 * 128];
    int tid = threadIdx.x, tx = tid & 15, ty = tid >> 4;
    int mblk = blockIdx.x, nblk = blockIdx.y;
    float acc[8][8];
#pragma unroll
    for (int i = 0; i < 8; i++)
#pragma unroll
        for (int j = 0; j < 8; j++) acc[i][j] = 0.f;

    for (int kb = 0; kb < E_SZ; kb += 16) {
#pragma unroll
        for (int u = 0; u < 2; u++) {
            int idx = tid + u * 256, row = idx >> 2, kq = idx & 3;
            int r = mblk * 128 + row;
            int w = (r < NROWS) ? words[(r & 31) * T_SZ + (r >> 5)] : 0;
            float4 v = *(const float4*)(embW + (size_t)w * E_SZ + kb + kq * 4);
            if (r >= NROWS) v = make_float4(0.f, 0.f, 0.f, 0.f);
            As[(kq * 4 + 0) * 128 + row] = v.x;
            As[(kq * 4 + 1) * 128 + row] = v.y;
            As[(kq * 4 + 2) * 128 + row] = v.z;
            As[(kq * 4 + 3) * 128 + row] = v.w;
        }
#pragma unroll
        for (int u = 0; u < 2; u++) {
            int idx = tid + u * 256, col = idx >> 2, kq = idx & 3;
            int c = nblk * 128 + col;
            float4 v = *(const float4*)(Wih + (size_t)c * E_SZ + kb + kq * 4);
            Bs[(kq * 4 + 0) * 128 + col] = v.x;
            Bs[(kq * 4 + 1) * 128 + col] = v.y;
            Bs[(kq * 4 + 2) * 128 + col] = v.z;
            Bs[(kq * 4 + 3) * 128 + col] = v.w;
        }
        __syncthreads();
#pragma unroll
        for (int k = 0; k < 16; k++) {
            float a[8], bb[8];
            *(float4*)(a)      = *(const float4*)&As[k * 128 + ty * 4];
            *(float4*)(a + 4)  = *(const float4*)&As[k * 128 + 64 + ty * 4];
            *(float4*)(bb)     = *(const float4*)&Bs[k * 128 + tx * 4];
            *(float4*)(bb + 4) = *(const float4*)&Bs[k * 128 + 64 + tx * 4];
#pragma unroll
            for (int i = 0; i < 8; i++)
#pragma unroll
                for (int j = 0; j < 8; j++) acc[i][j] += a[i] * bb[j];
        }
        __syncthreads();
    }
#pragma unroll
    for (int i = 0; i < 8; i++) {
        int r = mblk * 128 + ((i < 4) ? ty * 4 + i : 64 + ty * 4 + (i - 4));
#pragma unroll
        for (int j = 0; j < 8; j++) {
            int c = nblk * 128 + ((j < 4) ? tx * 4 + j : 64 + tx * 4 + (j - 4));
            g_gi[(size_t)r * C3H + c] = acc[i][j] + bih[c];
        }
    }
}

// ---------------- grid barrier ----------------
__device__ __forceinline__ void gridbar() {
    __syncthreads();
    if (threadIdx.x == 0) {
        unsigned int gen = *((volatile unsigned int*)&g_bargen);
        __threadfence();
        unsigned int t = atomicAdd(&g_barcnt, 1u);
        if (t == REC_CTAS - 1) {
            g_barcnt = 0;
            __threadfence();
            *((volatile unsigned int*)&g_bargen) = gen + 1;
        } else {
            while (*((volatile unsigned int*)&g_bargen) == gen) { __nanosleep(64); }
        }
        __threadfence();
    }
    __syncthreads();
}

// ---------------- kernel 2: persistent GRU recurrence ----------------
__global__ __launch_bounds__(256) void k_rec(const float* __restrict__ h0,
                                             const float* __restrict__ Whh,
                                             const float* __restrict__ bhh) {
    extern __shared__ float sm[];
    float* sW   = sm;                  // 512*12
    float* sH   = sW + 512 * 12;       // 32*513
    float* red  = sH + 32 * 513;       // 256*12
    float* ghs  = red + 256 * 12;      // 384
    float* sbhh = ghs + 384;           // 12

    int tid = threadIdx.x, cta = blockIdx.x;

    for (int i = tid; i < 12 * 512; i += 256) {
        int cl = i >> 9, k = i & 511;
        int row = (cl >> 2) * H_SZ + cta * 4 + (cl & 3);
        sW[k * 12 + cl] = Whh[(size_t)row * H_SZ + k];
    }
    if (tid < 12) sbhh[tid] = bhh[(tid >> 2) * H_SZ + cta * 4 + (tid & 3)];

    for (int i = tid; i < 128; i += 256) g_hall[cta * 128 + i] = h0[cta * 128 + i];
    __threadfence();
    gridbar();

    int lane = tid & 31, wid = tid >> 5;
    int bq = lane & 7, cg = lane >> 3, k0 = wid * 64;

    for (int t = 0; t < NSTEP; t++) {
        const float* hsrc = g_hall + (size_t)t * N_B * H_SZ;
        for (int i = tid; i < N_B * H_SZ / 4; i += 256) {
            float4 v = ((const float4*)hsrc)[i];
            int flat = i * 4, b = flat >> 9, k = flat & 511;
            float* p = &sH[b * 513 + k];
            p[0] = v.x; p[1] = v.y; p[2] = v.z; p[3] = v.w;
        }
        __syncthreads();

        float acc[3][4];
#pragma unroll
        for (int c = 0; c < 3; c++)
#pragma unroll
            for (int b = 0; b < 4; b++) acc[c][b] = 0.f;

#pragma unroll 4
        for (int kk = 0; kk < 64; kk++) {
            int k = k0 + kk;
            float h0v = sH[(bq * 4 + 0) * 513 + k];
            float h1v = sH[(bq * 4 + 1) * 513 + k];
            float h2v = sH[(bq * 4 + 2) * 513 + k];
            float h3v = sH[(bq * 4 + 3) * 513 + k];
            float w0 = sW[k * 12 + cg * 3 + 0];
            float w1 = sW[k * 12 + cg * 3 + 1];
            float w2 = sW[k * 12 + cg * 3 + 2];
            acc[0][0] += h0v * w0; acc[0][1] += h1v * w0; acc[0][2] += h2v * w0; acc[0][3] += h3v * w0;
            acc[1][0] += h0v * w1; acc[1][1] += h1v * w1; acc[1][2] += h2v * w1; acc[1][3] += h3v * w1;
            acc[2][0] += h0v * w2; acc[2][1] += h1v * w2; acc[2][2] += h2v * w2; acc[2][3] += h3v * w2;
        }
        {
            float* rp = &red[tid * 12];
#pragma unroll
            for (int c = 0; c < 3; c++)
#pragma unroll
                for (int b = 0; b < 4; b++) rp[c * 4 + b] = acc[c][b];
        }
        __syncthreads();

        for (int o = tid; o < 384; o += 256) {
            int cl = o >> 5, b = o & 31;
            int l = (b >> 2) + 8 * (cl / 3);
            int a = (cl % 3) * 4 + (b & 3);
            float s = 0.f;
#pragma unroll
            for (int w = 0; w < 8; w++) s += red[(w * 32 + l) * 12 + a];
            ghs[o] = s;
        }
        __syncthreads();

        if (tid < 128) {
            int jl = tid >> 5, b = tid & 31;
            float ghr = ghs[(0 + jl) * 32 + b] + sbhh[0 + jl];
            float ghz = ghs[(4 + jl) * 32 + b] + sbhh[4 + jl];
            float ghn = ghs[(8 + jl) * 32 + b] + sbhh[8 + jl];
            const float* gi = &g_gi[(size_t)(t * N_B + b) * C3H + cta * 4 + jl];
            float r = 1.f / (1.f + expf(-(gi[0] + ghr)));
            float z = 1.f / (1.f + expf(-(gi[512] + ghz)));
            float n = tanhf(gi[1024] + r * ghn);
            float hold = sH[b * 513 + (cta * 4 + jl)];
            g_hall[(size_t)(t + 1) * N_B * H_SZ + (size_t)b * H_SZ + cta * 4 + jl] =
                (1.f - z) * n + z * hold;
        }
        __threadfence();
        gridbar();
    }
}

// ---------------- kernel 3: target logits ----------------
__global__ __launch_bounds__(256) void k_tgt(const int* __restrict__ words,
                                             const float* __restrict__ emW,
                                             const float* __restrict__ emb) {
    int gw = blockIdx.x * 8 + (threadIdx.x >> 5);
    int lane = threadIdx.x & 31;
    if (gw >= NROWS) return;
    int t = gw >> 5, b = gw & 31;
    int tgt = words[b * T_SZ + t + 1];
    const float* hr = g_hall + (size_t)(gw + N_B) * H_SZ;
    const float* wr = emW + (size_t)tgt * E_SZ;
    float s = 0.f;
#pragma unroll
    for (int q = 0; q < 4; q++) {
        int k = q * 128 + lane * 4;
        float4 hv = *(const float4*)(hr + k);
        float4 wv = *(const float4*)(wr + k);
        s += hv.x * wv.x + hv.y * wv.y + hv.z * wv.z + hv.w * wv.w;
    }
#pragma unroll
    for (int off = 16; off; off >>= 1) s += __shfl_down_sync(0xffffffffu, s, off);
    if (lane == 0) g_tlog[gw] = s + emb[tgt];
}

// ---------------- tf32 helpers ----------------
__device__ __forceinline__ uint32_t f2tf32(float x) {
    uint32_t r;
    asm("cvt.rna.tf32.f32 %0, %1;" : "=r"(r) : "f"(x));
    return r;
}

__device__ __forceinline__ void mma_tf32(float* d, const uint32_t* a, const uint32_t* b) {
    asm volatile(
        "mma.sync.aligned.m16n8k8.row.col.f32.tf32.tf32.f32 "
        "{%0,%1,%2,%3}, {%4,%5,%6,%7}, {%8,%9}, {%0,%1,%2,%3};"
        : "+f"(d[0]), "+f"(d[1]), "+f"(d[2]), "+f"(d[3])
        : "r"(a[0]), "r"(a[1]), "r"(a[2]), "r"(a[3]), "r"(b[0]), "r"(b[1]));
}

// ---------------- kernel 4: logits GEMM (tf32 tensor-core) + fused partial LSE ----
// 128x128 CTA tile, 8 warps as 2(M) x 4(N); warp tile 64x32 via m16n8k8 tf32 mma.
// smem A/B staged [row][k] with stride 20 (conflict-free fragment LDS).
__global__ __launch_bounds__(256) void k_logits(const float* __restrict__ emW,
                                                const float* __restrict__ emb) {
    __shared__ float As[128 * 20];
    __shared__ float Bs[128 * 20];
    __shared__ float red[128 * 4];
    __shared__ float rowst[128];
    __shared__ float bs[128];
    const float* Amat = g_hall + N_B * H_SZ;

    int tid = threadIdx.x;
    int lane = tid & 31, wid = tid >> 5;
    int warpM = wid >> 2, warpN = wid & 3;     // 2 x 4 warp grid
    int lr = lane >> 2, lc = lane & 3;          // fragment row-group / col-in-group
    int mblk = blockIdx.x, nblk = blockIdx.y;

    if (tid < 128) {
        int c = nblk * 128 + tid;
        bs[tid] = (c < V_SZ) ? emb[c] : -1.0e30f;   // -inf bias masks invalid cols
    }

    float acc[4][4][4];
#pragma unroll
    for (int mi = 0; mi < 4; mi++)
#pragma unroll
        for (int ni = 0; ni < 4; ni++)
#pragma unroll
            for (int q = 0; q < 4; q++) acc[mi][ni][q] = 0.f;

    for (int kb = 0; kb < E_SZ; kb += 16) {
#pragma unroll
        for (int u = 0; u < 2; u++) {
            int idx = tid + u * 256;               // 0..511
            int m = idx >> 2, kq = idx & 3;
            float4 v = *(const float4*)(Amat + (size_t)(mblk * 128 + m) * E_SZ + kb + kq * 4);
            *(float4*)&As[m * 20 + kq * 4] = v;
        }
#pragma unroll
        for (int u = 0; u < 2; u++) {
            int idx = tid + u * 256;
            int n = idx >> 2, kq = idx & 3;
            int c = nblk * 128 + n;
            float4 v = make_float4(0.f, 0.f, 0.f, 0.f);
            if (c < V_SZ) v = *(const float4*)(emW + (size_t)c * E_SZ + kb + kq * 4);
            *(float4*)&Bs[n * 20 + kq * 4] = v;
        }
        __syncthreads();

#pragma unroll
        for (int ks = 0; ks < 2; ks++) {
            int k0 = ks * 8;
            uint32_t af[4][4], bf[4][2];
#pragma unroll
            for (int mi = 0; mi < 4; mi++) {
                const float* ap = &As[(warpM * 64 + mi * 16 + lr) * 20 + k0 + lc];
                af[mi][0] = f2tf32(ap[0]);
                af[mi][1] = f2tf32(ap[8 * 20]);        // row +8
                af[mi][2] = f2tf32(ap[4]);             // k +4
                af[mi][3] = f2tf32(ap[8 * 20 + 4]);
            }
#pragma unroll
            for (int ni = 0; ni < 4; ni++) {
                const float* bp = &Bs[(warpN * 32 + ni * 8 + lr) * 20 + k0 + lc];
                bf[ni][0] = f2tf32(bp[0]);
                bf[ni][1] = f2tf32(bp[4]);             // k +4
            }
#pragma unroll
            for (int mi = 0; mi < 4; mi++)
#pragma unroll
                for (int ni = 0; ni < 4; ni++)
                    mma_tf32(acc[mi][ni], af[mi], bf[ni]);
        }
        __syncthreads();
    }

    // ---- epilogue: bias + per-row (max, sumexp) over this 128-col block ----
#pragma unroll
    for (int mi = 0; mi < 4; mi++)
#pragma unroll
        for (int ni = 0; ni < 4; ni++) {
            int c0 = warpN * 32 + ni * 8 + lc * 2;
            float b0v = bs[c0], b1v = bs[c0 + 1];
            acc[mi][ni][0] += b0v; acc[mi][ni][1] += b1v;
            acc[mi][ni][2] += b0v; acc[mi][ni][3] += b1v;
        }

    // row max (rows r = warpM*64+mi*16+lr and r+8)
#pragma unroll
    for (int mi = 0; mi < 4; mi++) {
        float m0 = -3.0e38f, m1 = -3.0e38f;
#pragma unroll
        for (int ni = 0; ni < 4; ni++) {
            m0 = fmaxf(m0, fmaxf(acc[mi][ni][0], acc[mi][ni][1]));
            m1 = fmaxf(m1, fmaxf(acc[mi][ni][2], acc[mi][ni][3]));
        }
        m0 = fmaxf(m0, __shfl_xor_sync(0xffffffffu, m0, 1));
        m0 = fmaxf(m0, __shfl_xor_sync(0xffffffffu, m0, 2));
        m1 = fmaxf(m1, __shfl_xor_sync(0xffffffffu, m1, 1));
        m1 = fmaxf(m1, __shfl_xor_sync(0xffffffffu, m1, 2));
        if (lc == 0) {
            int r0 = warpM * 64 + mi * 16 + lr;
            red[r0 * 4 + warpN] = m0;
            red[(r0 + 8) * 4 + warpN] = m1;
        }
    }
    __syncthreads();
    if (tid < 128) {
        float m = red[tid * 4 + 0];
        m = fmaxf(m, red[tid * 4 + 1]);
        m = fmaxf(m, red[tid * 4 + 2]);
        m = fmaxf(m, red[tid * 4 + 3]);
        rowst[tid] = m;
    }
    __syncthreads();

    // row sumexp
#pragma unroll
    for (int mi = 0; mi < 4; mi++) {
        int r0 = warpM * 64 + mi * 16 + lr;
        float M0 = rowst[r0], M1 = rowst[r0 + 8];
        float s0 = 0.f, s1 = 0.f;
#pragma unroll
        for (int ni = 0; ni < 4; ni++) {
            s0 += expf(acc[mi][ni][0] - M0) + expf(acc[mi][ni][1] - M0);
            s1 += expf(acc[mi][ni][2] - M1) + expf(acc[mi][ni][3] - M1);
        }
        s0 += __shfl_xor_sync(0xffffffffu, s0, 1);
        s0 += __shfl_xor_sync(0xffffffffu, s0, 2);
        s1 += __shfl_xor_sync(0xffffffffu, s1, 1);
        s1 += __shfl_xor_sync(0xffffffffu, s1, 2);
        if (lc == 0) {
            red[r0 * 4 + warpN] = s0;
            red[(r0 + 8) * 4 + warpN] = s1;
        }
    }
    __syncthreads();
    if (tid < 128) {
        float s = red[tid * 4 + 0] + red[tid * 4 + 1] + red[tid * 4 + 2] + red[tid * 4 + 3];
        int rg = mblk * 128 + tid;
        g_pmax[(size_t)nblk * NROWS_PAD + rg] = rowst[tid];
        g_psum[(size_t)nblk * NROWS_PAD + rg] = s;
    }
}

// ---------------- kernel 5: combine partials -> ll ----------------
__global__ __launch_bounds__(256) void k_fin1() {
    int row = blockIdx.x * 256 + threadIdx.x;
    if (row >= NROWS) return;
    float m = -3.0e38f;
    for (int blk = 0; blk < NBLK_V; blk++)
        m = fmaxf(m, g_pmax[(size_t)blk * NROWS_PAD + row]);
    float s = 0.f;
    for (int blk = 0; blk < NBLK_V; blk++)
        s += g_psum[(size_t)blk * NROWS_PAD + row] *
             expf(g_pmax[(size_t)blk * NROWS_PAD + row] - m);
    g_ll[row] = g_tlog[row] - (m + logf(s));
}

// ---------------- kernel 6: outputs ----------------
__global__ __launch_bounds__(256) void k_out(float* __restrict__ out) {
    int i = blockIdx.x * 256 + threadIdx.x;
    if (i < 32) {
        float s = 0.f;
        for (int t = 0; t < NSTEP; t++) s += g_ll[t * 32 + i];
        out[i] = s * (1.0f / (float)NSTEP);
    }
    int j = i - 32;
    if (j >= 0 && j < N_B * H_SZ)
        out[32 + j] = g_hall[(size_t)NSTEP * N_B * H_SZ + j];
}

extern "C" void kernel_launch(void* const* d_in, const int* in_sizes, int n_in,
                              void* d_out, int out_size) {
    const int*   words = (const int*)d_in[0];
    const float* h0    = (const float*)d_in[1];
    const float* embW  = (const float*)d_in[2];
    const float* Wih   = (const float*)d_in[3];
    const float* Whh   = (const float*)d_in[4];
    const float* bih   = (const float*)d_in[5];
    const float* bhh   = (const float*)d_in[6];
    const float* emW   = (const float*)d_in[7];
    const float* emb   = (const float*)d_in[8];
    float* out = (float*)d_out;

    const int rec_smem = (512 * 12 + 32 * 513 + 256 * 12 + 384 + 12) * 4;
    cudaFuncSetAttribute(k_rec, cudaFuncAttributeMaxDynamicSharedMemorySize, rec_smem);

    k_gi<<<dim3(32, 12), 256>>>(words, embW, Wih, bih);
    k_rec<<<REC_CTAS, 256, rec_smem>>>(h0, Whh, bhh);
    k_tgt<<<(NROWS + 7) / 8, 256>>>(words, emW, emb);
    k_logits<<<dim3(32, NBLK_V), 256>>>(emW, emb);
    k_fin1<<<(NROWS + 255) / 256, 256>>>();
    k_out<<<(32 + N_B * H_SZ + 255) / 256, 256>>>(out);
}